// round 2
// baseline (speedup 1.0000x reference)
#include <cuda_runtime.h>
#include <math.h>

#define Bb 8
#define Qn 128
#define Kn 256
#define Dd 512
#define Hh 512
#define Vv 512
#define HUGEF 1000000000.0f

// Scratch (allocation-free rule: __device__ globals)
__device__ float g_qproj[Bb*Qn*Hh];   // 2 MB
__device__ float g_kproj[Bb*Kn*Hh];   // 4 MB (b1 folded in)
__device__ float g_scores[Bb*Qn*Kn];  // 1 MB

__device__ __forceinline__ float fast_tanh(float x){
    float r; asm("tanh.approx.f32 %0, %1;" : "=f"(r) : "f"(x)); return r;
}

// ---------------------------------------------------------------------------
// Kernel 1: projections. Rows 0..1023 = query @ W1[:512]; rows 1024..3071 =
// key @ W1[512:] + b1. 64x64 tile, 256 threads, 4x4 micro-tile, k-chunk 16.
// ---------------------------------------------------------------------------
__global__ __launch_bounds__(256) void proj_kernel(const float* __restrict__ query,
                                                   const float* __restrict__ key,
                                                   const float* __restrict__ W1,
                                                   const float* __restrict__ b1){
    __shared__ float As[16][68];  // transposed [k][m], padded
    __shared__ float Ws[16][64];
    int tid = threadIdx.x;
    int colTile = blockIdx.x * 64;
    int rowTile = blockIdx.y * 64;
    bool isQ = rowTile < Bb*Qn;
    const float* A = isQ ? (query + (size_t)rowTile*Dd)
                         : (key + (size_t)(rowTile - Bb*Qn)*Dd);
    const float* W = W1 + (size_t)(isQ ? 0 : Dd)*Hh + colTile;

    int tx = tid & 15, ty = tid >> 4;
    int arow = tid >> 2;          // 0..63
    int ac4  = (tid & 3) * 4;     // 0,4,8,12
    int wrow = tid >> 4;          // 0..15
    int wc4  = (tid & 15) * 4;    // 0..60

    float acc[4][4];
    #pragma unroll
    for (int i = 0; i < 4; i++)
        #pragma unroll
        for (int j = 0; j < 4; j++) acc[i][j] = 0.0f;

    for (int k0 = 0; k0 < Dd; k0 += 16){
        float4 av = *(const float4*)(A + (size_t)arow*Dd + k0 + ac4);
        float4 wv = *(const float4*)(W + (size_t)(k0 + wrow)*Hh + wc4);
        __syncthreads();
        As[ac4+0][arow] = av.x; As[ac4+1][arow] = av.y;
        As[ac4+2][arow] = av.z; As[ac4+3][arow] = av.w;
        *(float4*)&Ws[wrow][wc4] = wv;
        __syncthreads();
        #pragma unroll
        for (int kk = 0; kk < 16; kk++){
            float4 a = *(const float4*)&As[kk][ty*4];
            float4 b = *(const float4*)&Ws[kk][tx*4];
            float ar[4] = {a.x, a.y, a.z, a.w};
            float br[4] = {b.x, b.y, b.z, b.w};
            #pragma unroll
            for (int i = 0; i < 4; i++)
                #pragma unroll
                for (int j = 0; j < 4; j++)
                    acc[i][j] += ar[i]*br[j];
        }
    }

    if (isQ){
        float* outp = g_qproj + (size_t)rowTile*Hh + colTile;
        #pragma unroll
        for (int i = 0; i < 4; i++)
            #pragma unroll
            for (int j = 0; j < 4; j++)
                outp[(size_t)(ty*4+i)*Hh + tx*4+j] = acc[i][j];
    } else {
        float* outp = g_kproj + (size_t)(rowTile - Bb*Qn)*Hh + colTile;
        #pragma unroll
        for (int i = 0; i < 4; i++)
            #pragma unroll
            for (int j = 0; j < 4; j++)
                outp[(size_t)(ty*4+i)*Hh + tx*4+j] = acc[i][j] + b1[colTile + tx*4+j];
    }
}

// ---------------------------------------------------------------------------
// Kernel 2: scores[b,q,k] = sum_h w2[h]*tanh(qp[b,q,h]+kp[b,k,h]).
// Block tile 32q x 64k, 256 threads (16 k-threads x 16 q-threads),
// micro-tile 2q x 4k, h staged in smem transposed chunks of 32.
// Mask + 1/sqrt(512) applied at epilogue. MUFU-bound.
// ---------------------------------------------------------------------------
__global__ __launch_bounds__(256) void score_kernel(const int* __restrict__ mask,
                                                    const float* __restrict__ w2){
    __shared__ float qs[32][36];  // [h][q]
    __shared__ float ks[32][68];  // [h][k]
    __shared__ float ws[32];
    int b  = blockIdx.z;
    int q0 = blockIdx.y * 32;
    int k0 = blockIdx.x * 64;
    int tid = threadIdx.x;
    int tx = tid & 15;    // k dim, TK=4
    int ty = tid >> 4;    // q dim, TQ=2
    const float* qbase = g_qproj + (size_t)(b*Qn + q0)*Hh;
    const float* kbase = g_kproj + (size_t)(b*Kn + k0)*Hh;

    float acc[2][4];
    #pragma unroll
    for (int i = 0; i < 2; i++)
        #pragma unroll
        for (int j = 0; j < 4; j++) acc[i][j] = 0.0f;

    int ql_r = tid >> 3;        // 0..31
    int ql_c = (tid & 7) * 4;   // 0..28
    int kl_r = tid >> 2;        // 0..63
    int kl_c = (tid & 3) * 4;   // 0..12

    for (int h0 = 0; h0 < Hh; h0 += 32){
        float4 qv4  = *(const float4*)(qbase + (size_t)ql_r*Hh + h0 + ql_c);
        float4 kv4a = *(const float4*)(kbase + (size_t)kl_r*Hh + h0 + kl_c);
        float4 kv4b = *(const float4*)(kbase + (size_t)kl_r*Hh + h0 + kl_c + 16);
        __syncthreads();
        qs[ql_c+0][ql_r] = qv4.x; qs[ql_c+1][ql_r] = qv4.y;
        qs[ql_c+2][ql_r] = qv4.z; qs[ql_c+3][ql_r] = qv4.w;
        ks[kl_c+0][kl_r] = kv4a.x; ks[kl_c+1][kl_r] = kv4a.y;
        ks[kl_c+2][kl_r] = kv4a.z; ks[kl_c+3][kl_r] = kv4a.w;
        ks[kl_c+16][kl_r] = kv4b.x; ks[kl_c+17][kl_r] = kv4b.y;
        ks[kl_c+18][kl_r] = kv4b.z; ks[kl_c+19][kl_r] = kv4b.w;
        if (tid < 32) ws[tid] = w2[h0 + tid];
        __syncthreads();
        #pragma unroll
        for (int h = 0; h < 32; h++){
            float wv = ws[h];
            float2 qv = *(const float2*)&qs[h][ty*2];
            float4 kv = *(const float4*)&ks[h][tx*4];
            float kr[4] = {kv.x, kv.y, kv.z, kv.w};
            #pragma unroll
            for (int j = 0; j < 4; j++){
                acc[0][j] += wv * fast_tanh(qv.x + kr[j]);
                acc[1][j] += wv * fast_tanh(qv.y + kr[j]);
            }
        }
    }

    const float rs = 0.04419417382415922f;  // 1/sqrt(512)
    #pragma unroll
    for (int j = 0; j < 4; j++){
        int kk = k0 + tx*4 + j;
        int m = mask[b*Kn + kk];
        #pragma unroll
        for (int i = 0; i < 2; i++){
            int qq = q0 + ty*2 + i;
            float s = (m != 0) ? -HUGEF : acc[i][j];
            g_scores[(size_t)(b*Qn + qq)*Kn + kk] = s * rs;
        }
    }
}

// ---------------------------------------------------------------------------
// Kernel 3: row softmax over K=256; writes attn_weights into d_out.
// ---------------------------------------------------------------------------
__global__ __launch_bounds__(256) void softmax_kernel(float* __restrict__ out_w){
    int row = blockIdx.x;     // 0..B*Q-1
    int t = threadIdx.x;      // 0..255
    int lane = t & 31, warp = t >> 5;
    __shared__ float red[8];
    float s = g_scores[(size_t)row*Kn + t];

    float m = s;
    #pragma unroll
    for (int o = 16; o > 0; o >>= 1) m = fmaxf(m, __shfl_xor_sync(0xffffffffu, m, o));
    if (lane == 0) red[warp] = m;
    __syncthreads();
    float m8 = red[0];
    #pragma unroll
    for (int i = 1; i < 8; i++) m8 = fmaxf(m8, red[i]);

    float e = __expf(s - m8);
    float sum = e;
    #pragma unroll
    for (int o = 16; o > 0; o >>= 1) sum += __shfl_xor_sync(0xffffffffu, sum, o);
    __syncthreads();
    if (lane == 0) red[warp] = sum;
    __syncthreads();
    float s8 = 0.0f;
    #pragma unroll
    for (int i = 0; i < 8; i++) s8 += red[i];

    out_w[(size_t)row*Kn + t] = e / s8;
}

// ---------------------------------------------------------------------------
// Kernel 4: attn_vec[b,q,v] = sum_k w[b,q,k] * value[b,k,v].
// Block = (v-half 256, q-tile 8, b). Weights tile in smem, coalesced value.
// ---------------------------------------------------------------------------
__global__ __launch_bounds__(256) void attnvec_kernel(const float* __restrict__ value,
                                                      const float* __restrict__ attn_w,
                                                      float* __restrict__ out_v){
    __shared__ float ws[8][Kn];
    int b  = blockIdx.z;
    int q0 = blockIdx.y * 8;
    int v  = blockIdx.x * 256 + threadIdx.x;

    for (int i = threadIdx.x; i < 8*Kn; i += 256){
        int qi = i >> 8;     // Kn == 256
        int ki = i & 255;
        ws[qi][ki] = attn_w[(size_t)(b*Qn + q0 + qi)*Kn + ki];
    }
    __syncthreads();

    float acc[8];
    #pragma unroll
    for (int i = 0; i < 8; i++) acc[i] = 0.0f;

    const float* vb = value + (size_t)b*Kn*Vv + v;
    #pragma unroll 4
    for (int k = 0; k < Kn; k++){
        float val = vb[(size_t)k*Vv];
        #pragma unroll
        for (int i = 0; i < 8; i++) acc[i] += ws[i][k] * val;
    }
    #pragma unroll
    for (int i = 0; i < 8; i++)
        out_v[(size_t)(b*Qn + q0 + i)*Vv + v] = acc[i];
}

// ---------------------------------------------------------------------------
extern "C" void kernel_launch(void* const* d_in, const int* in_sizes, int n_in,
                              void* d_out, int out_size){
    const float* query = (const float*)d_in[0];
    const float* key_  = (const float*)d_in[1];
    const float* value = (const float*)d_in[2];
    const int*   mask  = (const int*)  d_in[3];
    const float* W1    = (const float*)d_in[4];
    const float* b1    = (const float*)d_in[5];
    const float* w2    = (const float*)d_in[6];

    float* out = (float*)d_out;
    float* out_vec = out;                       // (B,Q,V)
    float* out_w   = out + (size_t)Bb*Qn*Vv;    // (B,Q,K)

    dim3 g1(Hh/64, (Bb*Qn + Bb*Kn)/64);         // (8, 48)
    proj_kernel<<<g1, 256>>>(query, key_, W1, b1);

    dim3 g2(Kn/64, Qn/32, Bb);                  // (4, 4, 8)
    score_kernel<<<g2, 256>>>(mask, w2);

    softmax_kernel<<<Bb*Qn, 256>>>(out_w);

    dim3 g4(Vv/256, Qn/8, Bb);                  // (2, 16, 8)
    attnvec_kernel<<<g4, 256>>>(value, out_w, out_vec);
}